// round 16
// baseline (speedup 1.0000x reference)
#include <cuda_runtime.h>
#include <cuda_fp16.h>
#include <math.h>
#include <stdint.h>

#define BB   8
#define NPOS 4096
#define CC   512
#define NH   8
#define DH   64
#define KDIM 512
#define MTOT (BB * NPOS)   /* 32768 */
#define NTOT (2 * CC)      /* 1024  */

// ---------------- scratch (device globals; no allocs) ----------------
__device__ unsigned short g_qr[(size_t)MTOT * CC];   // q_rope fp16 [n][512]
__device__ unsigned short g_qf[(size_t)MTOT * CC];   // q_feat fp16 [n][512]
// GEMM A: 256 mtiles x 8 kchunks x (128 rows x 64 halves, SW128) = 16KB blocks
__device__ unsigned short g_xA[(size_t)MTOT * KDIM];
// GEMM B: 8 jtiles x 8 kchunks x 16KB blocks
__device__ unsigned short g_wB[(size_t)NTOT * KDIM];
// kv operands: tiled (b*8+chblk)*64+nchunk -> (64 ch x 64 n, SW128) 8KB blocks
__device__ unsigned short g_krT[(size_t)BB * CC * NPOS];
__device__ unsigned short g_xT[(size_t)BB * CC * NPOS];
__device__ float g_kspart[256 * CC];
__device__ float g_ksum[BB * CC];
__device__ float g_kv_part[8 * BB * NH * DH * DH];
__device__ unsigned short g_kvT[BB * NH * DH * DH];  // kv^T fp16 [bh][e][d]

// ---------------- PTX helpers (sm_90-baseline, no 'a'-gated features) -------
__device__ __forceinline__ uint32_t smem_u32(const void* p) {
    uint32_t a;
    asm("{ .reg .u64 t; cvta.to.shared.u64 t, %1; cvt.u32.u64 %0, t; }"
        : "=r"(a) : "l"(p));
    return a;
}
#define MBAR_INIT(a, c) \
    asm volatile("mbarrier.init.shared.b64 [%0], %1;" ::"r"(a), "r"(c) : "memory")
#define MBAR_EXPECT_TX(a, n) \
    asm volatile("mbarrier.arrive.expect_tx.shared.b64 _, [%0], %1;" ::"r"(a), "r"(n) : "memory")
#define MBAR_WAIT(addr, parity) do {                                          \
    uint32_t _m = (uint32_t)(addr);                                           \
    uint32_t _p = (uint32_t)(parity);                                         \
    asm volatile(                                                             \
        "{\n\t.reg .pred P1;\n\t"                                             \
        "WAIT_LOOP_%=:\n\t"                                                   \
        "mbarrier.try_wait.parity.acquire.cta.shared::cta.b64 P1, [%0], %1, 0x989680;\n\t" \
        "@P1 bra.uni WAIT_DONE_%=;\n\t"                                       \
        "bra.uni WAIT_LOOP_%=;\n\t"                                           \
        "WAIT_DONE_%=:\n\t}" ::"r"(_m), "r"(_p) : "memory");                  \
} while (0)
#define FENCE_ASYNC() asm volatile("fence.proxy.async.shared::cta;" ::: "memory")
__device__ __forceinline__ void bulk_g2s(uint32_t dst, const void* src,
                                         uint32_t bytes, uint32_t mbar) {
    asm volatile(
        "cp.async.bulk.shared::cluster.global.mbarrier::complete_tx::bytes "
        "[%0], [%1], %2, [%3];"
        ::"r"(dst), "l"(src), "r"(bytes), "r"(mbar) : "memory");
}
__device__ __forceinline__ void ldmx4(uint32_t* r, uint32_t addr) {
    asm volatile("ldmatrix.sync.aligned.m8n8.x4.shared.b16 {%0,%1,%2,%3}, [%4];"
                 : "=r"(r[0]), "=r"(r[1]), "=r"(r[2]), "=r"(r[3]) : "r"(addr));
}
__device__ __forceinline__ void mma16816(float* d, const uint32_t* a,
                                         const uint32_t* b) {
    asm volatile(
        "mma.sync.aligned.m16n8k16.row.col.f32.f16.f16.f32 "
        "{%0,%1,%2,%3}, {%4,%5,%6,%7}, {%8,%9}, {%0,%1,%2,%3};"
        : "+f"(d[0]), "+f"(d[1]), "+f"(d[2]), "+f"(d[3])
        : "r"(a[0]), "r"(a[1]), "r"(a[2]), "r"(a[3]), "r"(b[0]), "r"(b[1]));
}
// fp16-accumulator variant: d[0]={row r: c,c+1}, d[1]={row r+8: c,c+1}
__device__ __forceinline__ void mma16816h(uint32_t* d, const uint32_t* a,
                                          const uint32_t* b) {
    asm volatile(
        "mma.sync.aligned.m16n8k16.row.col.f16.f16.f16.f16 "
        "{%0,%1}, {%2,%3,%4,%5}, {%6,%7}, {%0,%1};"
        : "+r"(d[0]), "+r"(d[1])
        : "r"(a[0]), "r"(a[1]), "r"(a[2]), "r"(a[3]), "r"(b[0]), "r"(b[1]));
}
__device__ __forceinline__ unsigned short f2h(float v) {
    return __half_as_ushort(__float2half_rn(v));
}
__device__ __forceinline__ float h2f(unsigned short u) {
    return __half2float(__ushort_as_half(u));
}
__device__ __forceinline__ uint32_t sw128(uint32_t off) {
    return off ^ ((off >> 3) & 0x70);
}

// ============================================================================
// K0a: x -> GEMM-A tiled/swizzled fp16 + kv-B (x^T) tiled/swizzled fp16
// grid (8, 64, 2) per launch; 4 launches cover b = bz0 + blockIdx.z
// ============================================================================
__global__ __launch_bounds__(256) void k_prep_x(const float* __restrict__ x,
                                                int bz0) {
    __shared__ unsigned short s_hi[64 * 72];
    int ct = blockIdx.x, nt = blockIdx.y, b = bz0 + blockIdx.z;
    int n0 = nt * 64, ch0 = ct * 64;
    int tid = threadIdx.x;
    const size_t abase = ((size_t)(b * 32 + (nt >> 1)) * 8 + ct) * 16384;
#pragma unroll
    for (int i = 0; i < 4; i++) {
        int f = tid + i * 256;
        int r = f >> 4, c4 = f & 15;
        size_t ro = (size_t)(b * NPOS + n0 + r) * KDIM + ch0 + c4 * 4;
        float4 v = *(const float4*)(x + ro);
        unsigned short hh[4] = {f2h(v.x), f2h(v.y), f2h(v.z), f2h(v.w)};
        uint2 hp;
        hp.x = (uint32_t)hh[1] << 16 | hh[0];
        hp.y = (uint32_t)hh[3] << 16 | hh[2];
        uint32_t row = (nt & 1) * 64 + r;
        *(uint2*)((char*)g_xA + abase + sw128(row * 128 + c4 * 8)) = hp;
#pragma unroll
        for (int j = 0; j < 4; j++) s_hi[(c4 * 4 + j) * 72 + r] = hh[j];
    }
    __syncthreads();
    const size_t tbase = ((size_t)((b * 8 + ct) * 64 + nt)) * 8192;
#pragma unroll
    for (int w = 0; w < 2; w++) {
        int id = tid + w * 256;
        int ch = id >> 3, seg = id & 7;
        uint4 v = *(const uint4*)(s_hi + ch * 72 + seg * 8);
        *(uint4*)((char*)g_xT + tbase + sw128(ch * 128 + seg * 16)) = v;
    }
}

// ============================================================================
// K0b: Wqk -> GEMM-B tiled/swizzled fp16
// ============================================================================
__global__ __launch_bounds__(256) void k_convert_w(const float* __restrict__ W) {
    int idx = blockIdx.x * 256 + threadIdx.x;
    int j = idx >> 7, q4 = idx & 127;
    float4 v = *(const float4*)(W + (size_t)j * KDIM + q4 * 4);
    unsigned short hh[4] = {f2h(v.x), f2h(v.y), f2h(v.z), f2h(v.w)};
    uint2 hp;
    hp.x = (uint32_t)hh[1] << 16 | hh[0];
    hp.y = (uint32_t)hh[3] << 16 | hh[2];
    size_t base = ((size_t)(j >> 7) * 8 + (q4 >> 4)) * 16384;
    *(uint2*)((char*)g_wB + base + sw128((j & 127) * 128 + (q4 & 15) * 8)) = hp;
}

// ============================================================================
// K1: HMMA fp16 GEMM qk = x @ Wqk^T; cp.async.bulk 3-stage mbarrier pipeline.
// This round: fp16 ACCUMULATORS in the mainloop (f16.f16.f16.f16 HMMA).
// ============================================================================
#define STG_BYTES 32768          /* A 16KB + B 16KB */
#define GEMM_SMEM (3 * STG_BYTES + 1024)

__global__ __launch_bounds__(256, 2) void k_gemm_mma(const float* __restrict__ bqk) {
    extern __shared__ char dsm[];
    __shared__ long long s_mbar[3];
    const uint32_t dynb  = smem_u32(dsm);
    const uint32_t tile0 = (dynb + 1023) & ~1023u;

    const int tid = threadIdx.x;
    const int wid = tid >> 5, lid = tid & 31;
    const int jt  = blockIdx.x;            // 0..7
    const int mt  = blockIdx.y;            // 0..255
    const int j00 = jt * 128;
    const int m00 = mt * 128;
    const int warp_m = (wid >> 2) * 64;
    const int n0     = (wid & 3) * 32;

    uint32_t mb[3] = {smem_u32(&s_mbar[0]), smem_u32(&s_mbar[1]),
                      smem_u32(&s_mbar[2])};
    if (tid == 0)
#pragma unroll
        for (int s = 0; s < 3; s++) MBAR_INIT(mb[s], 1);
    __syncthreads();

    auto issue = [&](int it) {
        int s = it % 3;
        MBAR_EXPECT_TX(mb[s], STG_BYTES);
        bulk_g2s(tile0 + s * STG_BYTES,
                 (char*)g_xA + ((size_t)mt * 8 + it) * 16384, 16384, mb[s]);
        bulk_g2s(tile0 + s * STG_BYTES + 16384,
                 (char*)g_wB + ((size_t)jt * 8 + it) * 16384, 16384, mb[s]);
    };
    if (tid == 0) { issue(0); issue(1); issue(2); }

    uint32_t acc[4][4][2] = {};   // f16x2 pairs: [mf][nf][row r / row r+8]
    const int a_r = (lid & 15);
    const int a_c = (lid >> 4);
    const int b_r = (lid & 7) + ((lid >> 4) << 3);
    const int b_c = (lid >> 3) & 1;

    for (int it = 0; it < 8; ++it) {
        const int s = it % 3;
        MBAR_WAIT(mb[s], (it / 3) & 1);
        const uint32_t ab = tile0 + s * STG_BYTES;
        const uint32_t bb = ab + 16384;
#pragma unroll
        for (int ks = 0; ks < 4; ++ks) {
            uint32_t ah[4][4], bh[4][2];
#pragma unroll
            for (int mf = 0; mf < 4; mf++) {
                uint32_t off = (uint32_t)(warp_m + mf * 16 + a_r) * 128 +
                               ks * 32 + a_c * 16;
                ldmx4(ah[mf], ab + sw128(off));
            }
#pragma unroll
            for (int nf2 = 0; nf2 < 2; nf2++) {
                uint32_t off = (uint32_t)(n0 + nf2 * 16 + b_r) * 128 +
                               ks * 32 + b_c * 16;
                uint32_t t[4];
                ldmx4(t, bb + sw128(off));
                bh[nf2 * 2][0] = t[0]; bh[nf2 * 2][1] = t[1];
                bh[nf2 * 2 + 1][0] = t[2]; bh[nf2 * 2 + 1][1] = t[3];
            }
#pragma unroll
            for (int mf = 0; mf < 4; mf++)
#pragma unroll
                for (int nf = 0; nf < 4; nf++)
                    mma16816h(acc[mf][nf], ah[mf], bh[nf]);
        }
        __syncthreads();
        if (it + 3 < 8 && tid == 0) { FENCE_ASYNC(); issue(it + 3); }
    }

    // ---------------- epilogue ----------------
    unsigned short* s_p0 = (unsigned short*)dsm;               // 128x136
    unsigned short* s_p1 = s_p0 + 128 * 136;
    float*          s_red = (float*)(s_p1 + 128 * 136);        // 2x128

    const bool is_k = (j00 >= CC);
    const int  jbase = (is_k ? j00 - CC : j00) + n0 + 2 * (lid & 3);
    float th[4], bx[4], by[4];
    bool  uhc[4];
#pragma unroll
    for (int nf = 0; nf < 4; nf++) {
        int jch = jbase + nf * 8;
        int j2  = jch >> 1;
        int jm  = j2 & 127;
        th[nf]  = exp2f(-(float)jm * (13.287712379549449f / 128.0f));
        uhc[nf] = (j2 < 128);
        float2 bv = *(const float2*)(bqk + j00 + n0 + nf * 8 + 2 * (lid & 3));
        bx[nf] = bv.x;
        by[nf] = bv.y;
    }

    float fsum[4][2] = {};
#pragma unroll
    for (int mf = 0; mf < 4; mf++)
#pragma unroll
        for (int ri = 0; ri < 2; ri++) {
            int   r_loc = warp_m + mf * 16 + (lid >> 2) + ri * 8;
            int   n  = (m00 + r_loc) & (NPOS - 1);
            float hf = (float)(n >> 6);
            float wf = (float)(n & 63);
#pragma unroll
            for (int nf = 0; nf < 4; nf++) {
                float2 dv = __half22float2(*(__half2*)&acc[mf][nf][ri]);
                float v0 = dv.x + bx[nf];
                float v1 = dv.y + by[nf];
                float f0 = (v0 > 0.f) ? (v0 + 1.f) : __expf(v0);
                float f1 = (v1 > 0.f) ? (v1 + 1.f) : __expf(v1);
                float s, c;
                __sincosf((uhc[nf] ? hf : wf) * th[nf], &s, &c);
                float ro0 = c * f0 - s * f1;
                float ro1 = c * f1 + s * f0;
                int c_loc = n0 + nf * 8 + 2 * (lid & 3);
                if (!is_k) {
                    s_p0[r_loc * 136 + c_loc]     = f2h(ro0);
                    s_p0[r_loc * 136 + c_loc + 1] = f2h(ro1);
                    s_p1[r_loc * 136 + c_loc]     = f2h(f0);
                    s_p1[r_loc * 136 + c_loc + 1] = f2h(f1);
                } else {
                    s_p0[c_loc * 136 + r_loc]       = f2h(ro0);
                    s_p0[(c_loc + 1) * 136 + r_loc] = f2h(ro1);
                    fsum[nf][0] += f0;
                    fsum[nf][1] += f1;
                }
            }
        }

    if (is_k) {
#pragma unroll
        for (int off = 4; off < 32; off <<= 1)
#pragma unroll
            for (int nf = 0; nf < 4; nf++) {
                fsum[nf][0] += __shfl_xor_sync(0xffffffffu, fsum[nf][0], off);
                fsum[nf][1] += __shfl_xor_sync(0xffffffffu, fsum[nf][1], off);
            }
        if (lid < 4) {
#pragma unroll
            for (int nf = 0; nf < 4; nf++) {
                s_red[(wid >> 2) * 128 + n0 + nf * 8 + 2 * lid]     = fsum[nf][0];
                s_red[(wid >> 2) * 128 + n0 + nf * 8 + 2 * lid + 1] = fsum[nf][1];
            }
        }
    }
    __syncthreads();

    if (!is_k) {
        const int r    = tid >> 1;
        const int half = tid & 1;
        size_t drow = (size_t)(m00 + r) * CC + j00 + half * 64;
        const uint4* sp0 = (const uint4*)(s_p0 + r * 136 + half * 64);
        const uint4* sp1 = (const uint4*)(s_p1 + r * 136 + half * 64);
        uint4* d0 = (uint4*)(g_qr + drow);
        uint4* d1 = (uint4*)(g_qf + drow);
#pragma unroll
        for (int i = 0; i < 8; i++) { d0[i] = sp0[i]; d1[i] = sp1[i]; }
    } else {
        const int b      = m00 >> 12;
        const int n0g    = m00 & (NPOS - 1);
        const int cblk0  = (jt - 4) * 2;
#pragma unroll
        for (int w = 0; w < 8; w++) {
            int id  = tid + w * 256;
            int blk = id >> 9;          // 0..3
            int cb  = blk >> 1, nb = blk & 1;
            int within = id & 511;
            int ch = within >> 3, seg = within & 7;
            size_t base = ((size_t)((b * 8 + cblk0 + cb) * 64) +
                           (n0g >> 6) + nb) * 8192;
            uint4 v = *(const uint4*)(s_p0 + (cb * 64 + ch) * 136 + nb * 64 + seg * 8);
            *(uint4*)((char*)g_krT + base + sw128(ch * 128 + seg * 16)) = v;
        }
        if (tid < 128)
            g_kspart[(size_t)mt * CC + (jt - 4) * 128 + tid] =
                s_red[tid] + s_red[128 + tid];
    }
}

// ============================================================================
// K1c: ksum final
// ============================================================================
__global__ void k_ksum_final() {
    int idx = blockIdx.x * 256 + threadIdx.x;  // 0..4095
    if (idx < BB * CC) {
        int b = idx >> 9, ch = idx & 511;
        float s = 0.f;
        for (int mt = b * 32; mt < b * 32 + 32; mt++)
            s += g_kspart[(size_t)mt * CC + ch];
        g_ksum[idx] = s;
    }
}

// ============================================================================
// K2: kv partials via HMMA + bulk-copy pipeline over pre-swizzled 8KB tiles
// ============================================================================
#define KV_STG 16384
#define KV_SMEM (3 * KV_STG + 1024)

__global__ __launch_bounds__(128) void k_kv_mma() {
    extern __shared__ char ksm[];
    __shared__ long long s_mbar[3];
    const uint32_t dynb  = smem_u32(ksm);
    const uint32_t tile0 = (dynb + 1023) & ~1023u;
    const int tid = threadIdx.x;
    const int wid = tid >> 5, lid = tid & 31;
    const int chunk = blockIdx.x;          // 0..7
    const int bh    = blockIdx.y;          // 0..63
    const int b = bh >> 3, h = bh & 7;
    const size_t blk0 = (size_t)(b * 8 + h) * 64 + chunk * 8;

    uint32_t mb[3] = {smem_u32(&s_mbar[0]), smem_u32(&s_mbar[1]),
                      smem_u32(&s_mbar[2])};
    if (tid == 0)
#pragma unroll
        for (int s = 0; s < 3; s++) MBAR_INIT(mb[s], 1);
    __syncthreads();

    auto issue = [&](int it) {
        int s = it % 3;
        MBAR_EXPECT_TX(mb[s], KV_STG);
        bulk_g2s(tile0 + s * KV_STG, (char*)g_krT + (blk0 + it) * 8192, 8192, mb[s]);
        bulk_g2s(tile0 + s * KV_STG + 8192, (char*)g_xT + (blk0 + it) * 8192, 8192,
                 mb[s]);
    };
    if (tid == 0) { issue(0); issue(1); issue(2); }

    float acc[8][4] = {};
    const int a_r = (lid & 15);
    const int a_c = (lid >> 4);
    const int b_r = (lid & 7) + ((lid >> 4) << 3);
    const int b_c = (lid >> 3) & 1;

    for (int it = 0; it < 8; ++it) {
        const int s = it % 3;
        MBAR_WAIT(mb[s], (it / 3) & 1);
        const uint32_t ab = tile0 + s * KV_STG;
        const uint32_t bb = ab + 8192;
#pragma unroll
        for (int ks = 0; ks < 4; ++ks) {
            uint32_t ah[4];
            ldmx4(ah, ab + sw128((uint32_t)(wid * 16 + a_r) * 128 + ks * 32 + a_c * 16));
            uint32_t bhf[8][2];
#pragma unroll
            for (int e2 = 0; e2 < 4; e2++) {
                uint32_t t[4];
                ldmx4(t, bb + sw128((uint32_t)(e2 * 16 + b_r) * 128 + ks * 32 + b_c * 16));
                bhf[e2 * 2][0] = t[0]; bhf[e2 * 2][1] = t[1];
                bhf[e2 * 2 + 1][0] = t[2]; bhf[e2 * 2 + 1][1] = t[3];
            }
#pragma unroll
            for (int ef = 0; ef < 8; ef++) mma16816(acc[ef], ah, bhf[ef]);
        }
        __syncthreads();
        if (it + 3 < 8 && tid == 0) { FENCE_ASYNC(); issue(it + 3); }
    }

    float* dst = g_kv_part + (size_t)(chunk * 64 + bh) * (DH * DH);
    const int r0 = wid * 16 + (lid >> 2);
    const int c0 = 2 * (lid & 3);
#pragma unroll
    for (int ef = 0; ef < 8; ef++) {
        *(float2*)&dst[r0 * DH + ef * 8 + c0] = make_float2(acc[ef][0], acc[ef][1]);
        *(float2*)&dst[(r0 + 8) * DH + ef * 8 + c0] = make_float2(acc[ef][2], acc[ef][3]);
    }
}

// kv final: sum partials, scale 1/n, write TRANSPOSED fp16 kv^T [bh][e][d]
__global__ void k_kv_final() {
    int idx = blockIdx.x * 256 + threadIdx.x;   // bh*4096 + d*64 + e
    float s = 0.f;
    for (int c2 = 0; c2 < 8; c2++) s += g_kv_part[(size_t)c2 * 64 * DH * DH + idx];
    int bh = idx >> 12;
    int d  = (idx >> 6) & 63;
    int e  = idx & 63;
    g_kvT[(bh << 12) + e * 64 + d] = f2h(s * (1.0f / (float)NPOS));
}

// ============================================================================
// K3: out = (q_rope @ kv) * z + LePE(x)  (HMMA core, R15 version)
// ============================================================================
#define KOUT_DYN (1024 + 8192 + 8192 + 64 * 68 * 4)   /* 34816 */

__global__ __launch_bounds__(256) void k_out(const float* __restrict__ x,
                                             const float* __restrict__ lepe_w,
                                             const float* __restrict__ lepe_b,
                                             float* __restrict__ out) {
    extern __shared__ char kob[];
    __shared__ float s_z[64];
    __shared__ float s_km[64];

    const uint32_t dynb  = smem_u32(kob);
    const uint32_t base  = (dynb + 1023) & ~1023u;
    char*  bp     = kob + (base - dynb);
    const uint32_t qr_u  = base;          // 8KB: q_rope tile, sw128
    const uint32_t kvT_u = base + 8192;   // 8KB: kv^T tile, sw128
    float* s_out = (float*)(bp + 16384);  // 64x68 fp32: qfeat then HMMA result

    int ntile = blockIdx.x;
    int hh    = blockIdx.y;
    int b     = blockIdx.z;
    int tid   = threadIdx.x;
    int n0    = ntile * 64;

#pragma unroll
    for (int i = 0; i < 4; i++) {
        int f = tid + i * 256;
        int r = f >> 4, cu = f & 15;
        uint2 v = *(const uint2*)(g_qf + (size_t)(b * NPOS + n0 + r) * CC +
                                  hh * DH + cu * 4);
        s_out[r * 68 + cu * 4 + 0] = h2f((unsigned short)(v.x & 0xffff));
        s_out[r * 68 + cu * 4 + 1] = h2f((unsigned short)(v.x >> 16));
        s_out[r * 68 + cu * 4 + 2] = h2f((unsigned short)(v.y & 0xffff));
        s_out[r * 68 + cu * 4 + 3] = h2f((unsigned short)(v.y >> 16));
    }
#pragma unroll
    for (int w = 0; w < 2; w++) {
        int id = tid + w * 256;
        int r = id >> 3, seg = id & 7;
        uint4 v = *(const uint4*)(g_qr + (size_t)(b * NPOS + n0 + r) * CC +
                                  hh * DH + seg * 8);
        *(uint4*)(bp + sw128(r * 128 + seg * 16)) = v;
        uint4 kvv = *(const uint4*)(g_kvT + ((b * NH + hh) << 12) + r * 64 + seg * 8);
        *(uint4*)(bp + 8192 + sw128(r * 128 + seg * 16)) = kvv;
    }
    if (tid < 64) s_km[tid] = g_ksum[b * CC + hh * DH + tid] * (1.0f / (float)NPOS);
    __syncthreads();

    if (tid < 64) {
        float dot = 0.f;
#pragma unroll
        for (int dd = 0; dd < 64; dd++) dot += s_out[tid * 68 + dd] * s_km[dd];
        s_z[tid] = 1.0f / (dot + 1e-6f);
    }
    __syncthreads();

    {
        const int wid = tid >> 5, lid = tid & 31;
        const int mrow = (wid & 3) * 16;
        const int ncol = (wid >> 2) * 32;
        const int a_r = (lid & 15);
        const int a_c = (lid >> 4);
        const int b_r = (lid & 7) + ((lid >> 4) << 3);
        const int b_c = (lid >> 3) & 1;
        float acc[4][4] = {};
#pragma unroll
        for (int ks = 0; ks < 4; ++ks) {
            uint32_t ah[4];
            ldmx4(ah, qr_u + sw128((uint32_t)(mrow + a_r) * 128 + ks * 32 + a_c * 16));
            uint32_t bh[4][2];
#pragma unroll
            for (int nf2 = 0; nf2 < 2; nf2++) {
                uint32_t t[4];
                ldmx4(t, kvT_u + sw128((uint32_t)(ncol + nf2 * 16 + b_r) * 128 +
                                       ks * 32 + b_c * 16));
                bh[nf2 * 2][0] = t[0]; bh[nf2 * 2][1] = t[1];
                bh[nf2 * 2 + 1][0] = t[2]; bh[nf2 * 2 + 1][1] = t[3];
            }
#pragma unroll
            for (int nf = 0; nf < 4; nf++) mma16816(acc[nf], ah, bh[nf]);
        }
        __syncthreads();
#pragma unroll
        for (int nf = 0; nf < 4; nf++) {
            int rr = mrow + (lid >> 2);
            int cc = ncol + nf * 8 + 2 * (lid & 3);
            s_out[rr * 68 + cc]       = acc[nf][0];
            s_out[rr * 68 + cc + 1]   = acc[nf][1];
            s_out[(rr + 8) * 68 + cc]     = acc[nf][2];
            s_out[(rr + 8) * 68 + cc + 1] = acc[nf][3];
        }
    }
    __syncthreads();

    int ty = tid >> 4, tx = tid & 15;
    int r0 = ty * 4, e0 = tx * 4;
    const int hi = ntile;
    float wloc[4][9], bloc[4];
#pragma unroll
    for (int j = 0; j < 4; j++) {
        int ch = hh * DH + e0 + j;
        bloc[j] = lepe_b[ch];
#pragma unroll
        for (int q = 0; q < 9; q++) wloc[j][q] = lepe_w[ch * 9 + q];
    }
#pragma unroll
    for (int ri = 0; ri < 4; ri++) {
        int r  = r0 + ri;
        int wi = r;
        int nn = n0 + r;
        float z = s_z[r];
        float4 av = *(const float4*)&s_out[r * 68 + e0];
        float pe[4] = {bloc[0], bloc[1], bloc[2], bloc[3]};
#pragma unroll
        for (int dy = -1; dy <= 1; dy++) {
            int y = hi + dy;
            if ((unsigned)y < 64u) {
#pragma unroll
                for (int dx = -1; dx <= 1; dx++) {
                    int xw = wi + dx;
                    if ((unsigned)xw < 64u) {
                        float4 xv = *(const float4*)(
                            x + ((size_t)b * NPOS + y * 64 + xw) * CC +
                            hh * DH + e0);
                        int q = (dy + 1) * 3 + dx + 1;
                        pe[0] += wloc[0][q] * xv.x;
                        pe[1] += wloc[1][q] * xv.y;
                        pe[2] += wloc[2][q] * xv.z;
                        pe[3] += wloc[3][q] * xv.w;
                    }
                }
            }
        }
        float4 ov = make_float4(av.x * z + pe[0], av.y * z + pe[1],
                                av.z * z + pe[2], av.w * z + pe[3]);
        *(float4*)(out + ((size_t)b * NPOS + nn) * CC + hh * DH + e0) = ov;
    }
}

// ============================================================================
extern "C" void kernel_launch(void* const* d_in, const int* in_sizes, int n_in,
                              void* d_out, int out_size) {
    const float *x = nullptr, *Wqk = nullptr, *bqk = nullptr;
    const float *lw = nullptr, *lb = nullptr;
    for (int i = 0; i < n_in; i++) {
        switch (in_sizes[i]) {
            case BB * NPOS * CC: x   = (const float*)d_in[i]; break;
            case 2 * CC * CC:    Wqk = (const float*)d_in[i]; break;
            case 2 * CC:         bqk = (const float*)d_in[i]; break;
            case CC * 9:         lw  = (const float*)d_in[i]; break;
            case CC:             lb  = (const float*)d_in[i]; break;
            default: break;  // h, w scalars
        }
    }
    float* out = (float*)d_out;

    cudaFuncSetAttribute(k_gemm_mma, cudaFuncAttributeMaxDynamicSharedMemorySize,
                         GEMM_SMEM);
    cudaFuncSetAttribute(k_kv_mma, cudaFuncAttributeMaxDynamicSharedMemorySize,
                         KV_SMEM);
    cudaFuncSetAttribute(k_out, cudaFuncAttributeMaxDynamicSharedMemorySize,
                         KOUT_DYN);

    // 4 prep launches + convert_w => k_gemm_mma is launch index 5 (ncu -s 5 -c 1)
    k_prep_x<<<dim3(8, 64, 2), 256>>>(x, 0);
    k_prep_x<<<dim3(8, 64, 2), 256>>>(x, 2);
    k_prep_x<<<dim3(8, 64, 2), 256>>>(x, 4);
    k_prep_x<<<dim3(8, 64, 2), 256>>>(x, 6);
    k_convert_w<<<512, 256>>>(Wqk);
    k_gemm_mma<<<dim3(8, 256), 256, GEMM_SMEM>>>(bqk);
    k_ksum_final<<<16, 256>>>();
    k_kv_mma<<<dim3(8, 64), 128, KV_SMEM>>>();
    k_kv_final<<<1024, 256>>>();
    k_out<<<dim3(64, 8, 8), 256, KOUT_DYN>>>(x, lw, lb, out);
}

// round 17
// speedup vs baseline: 1.4855x; 1.4855x over previous
#include <cuda_runtime.h>
#include <cuda_fp16.h>
#include <math.h>
#include <stdint.h>

#define BB   8
#define NPOS 4096
#define CC   512
#define NH   8
#define DH   64
#define KDIM 512
#define MTOT (BB * NPOS)   /* 32768 */
#define NTOT (2 * CC)      /* 1024  */

// ---------------- scratch (device globals; no allocs) ----------------
__device__ unsigned short g_qr[(size_t)MTOT * CC];   // q_rope fp16 [n][512]
__device__ unsigned short g_qf[(size_t)MTOT * CC];   // q_feat fp16 [n][512]
// GEMM A: 256 mtiles x 8 kchunks x (128 rows x 64 halves, SW128) = 16KB blocks
__device__ unsigned short g_xA[(size_t)MTOT * KDIM];
// GEMM B: 8 jtiles x 8 kchunks x 16KB blocks
__device__ unsigned short g_wB[(size_t)NTOT * KDIM];
// kv operands: tiled (b*8+chblk)*64+nchunk -> (64 ch x 64 n, SW128) 8KB blocks
__device__ unsigned short g_krT[(size_t)BB * CC * NPOS];
__device__ unsigned short g_xT[(size_t)BB * CC * NPOS];
__device__ float g_kspart[256 * CC];
__device__ float g_ksum[BB * CC];
__device__ float g_kv_part[8 * BB * NH * DH * DH];
__device__ unsigned short g_kvT[BB * NH * DH * DH];  // kv^T fp16 [bh][e][d]

// ---------------- PTX helpers (sm_90-baseline, no 'a'-gated features) -------
__device__ __forceinline__ uint32_t smem_u32(const void* p) {
    uint32_t a;
    asm("{ .reg .u64 t; cvta.to.shared.u64 t, %1; cvt.u32.u64 %0, t; }"
        : "=r"(a) : "l"(p));
    return a;
}
#define MBAR_INIT(a, c) \
    asm volatile("mbarrier.init.shared.b64 [%0], %1;" ::"r"(a), "r"(c) : "memory")
#define MBAR_EXPECT_TX(a, n) \
    asm volatile("mbarrier.arrive.expect_tx.shared.b64 _, [%0], %1;" ::"r"(a), "r"(n) : "memory")
#define MBAR_WAIT(addr, parity) do {                                          \
    uint32_t _m = (uint32_t)(addr);                                           \
    uint32_t _p = (uint32_t)(parity);                                         \
    asm volatile(                                                             \
        "{\n\t.reg .pred P1;\n\t"                                             \
        "WAIT_LOOP_%=:\n\t"                                                   \
        "mbarrier.try_wait.parity.acquire.cta.shared::cta.b64 P1, [%0], %1, 0x989680;\n\t" \
        "@P1 bra.uni WAIT_DONE_%=;\n\t"                                       \
        "bra.uni WAIT_LOOP_%=;\n\t"                                           \
        "WAIT_DONE_%=:\n\t}" ::"r"(_m), "r"(_p) : "memory");                  \
} while (0)
#define FENCE_ASYNC() asm volatile("fence.proxy.async.shared::cta;" ::: "memory")
__device__ __forceinline__ void bulk_g2s(uint32_t dst, const void* src,
                                         uint32_t bytes, uint32_t mbar) {
    asm volatile(
        "cp.async.bulk.shared::cluster.global.mbarrier::complete_tx::bytes "
        "[%0], [%1], %2, [%3];"
        ::"r"(dst), "l"(src), "r"(bytes), "r"(mbar) : "memory");
}
__device__ __forceinline__ void ldmx4(uint32_t* r, uint32_t addr) {
    asm volatile("ldmatrix.sync.aligned.m8n8.x4.shared.b16 {%0,%1,%2,%3}, [%4];"
                 : "=r"(r[0]), "=r"(r[1]), "=r"(r[2]), "=r"(r[3]) : "r"(addr));
}
__device__ __forceinline__ void mma16816(float* d, const uint32_t* a,
                                         const uint32_t* b) {
    asm volatile(
        "mma.sync.aligned.m16n8k16.row.col.f32.f16.f16.f32 "
        "{%0,%1,%2,%3}, {%4,%5,%6,%7}, {%8,%9}, {%0,%1,%2,%3};"
        : "+f"(d[0]), "+f"(d[1]), "+f"(d[2]), "+f"(d[3])
        : "r"(a[0]), "r"(a[1]), "r"(a[2]), "r"(a[3]), "r"(b[0]), "r"(b[1]));
}
__device__ __forceinline__ unsigned short f2h(float v) {
    return __half_as_ushort(__float2half_rn(v));
}
__device__ __forceinline__ float h2f(unsigned short u) {
    return __half2float(__ushort_as_half(u));
}
__device__ __forceinline__ uint32_t sw128(uint32_t off) {
    return off ^ ((off >> 3) & 0x70);
}

// ============================================================================
// K0a: x -> GEMM-A tiled/swizzled fp16 + kv-B (x^T) tiled/swizzled fp16
// grid (8, 64, 2) per launch; 4 launches cover b = bz0 + blockIdx.z
// ============================================================================
__global__ __launch_bounds__(256) void k_prep_x(const float* __restrict__ x,
                                                int bz0) {
    __shared__ unsigned short s_hi[64 * 72];
    int ct = blockIdx.x, nt = blockIdx.y, b = bz0 + blockIdx.z;
    int n0 = nt * 64, ch0 = ct * 64;
    int tid = threadIdx.x;
    // GEMM A tile block: mt = b*32 + nt/2, kchunk = ct, row = (nt&1)*64 + r
    const size_t abase = ((size_t)(b * 32 + (nt >> 1)) * 8 + ct) * 16384;
#pragma unroll
    for (int i = 0; i < 4; i++) {
        int f = tid + i * 256;
        int r = f >> 4, c4 = f & 15;
        size_t ro = (size_t)(b * NPOS + n0 + r) * KDIM + ch0 + c4 * 4;
        float4 v = *(const float4*)(x + ro);
        unsigned short hh[4] = {f2h(v.x), f2h(v.y), f2h(v.z), f2h(v.w)};
        uint2 hp;
        hp.x = (uint32_t)hh[1] << 16 | hh[0];
        hp.y = (uint32_t)hh[3] << 16 | hh[2];
        uint32_t row = (nt & 1) * 64 + r;
        *(uint2*)((char*)g_xA + abase + sw128(row * 128 + c4 * 8)) = hp;
#pragma unroll
        for (int j = 0; j < 4; j++) s_hi[(c4 * 4 + j) * 72 + r] = hh[j];
    }
    __syncthreads();
    // kv x^T tile: block (b*8+ct)*64 + nt : [ch 64][n 64] swizzled
    const size_t tbase = ((size_t)((b * 8 + ct) * 64 + nt)) * 8192;
#pragma unroll
    for (int w = 0; w < 2; w++) {
        int id = tid + w * 256;
        int ch = id >> 3, seg = id & 7;
        uint4 v = *(const uint4*)(s_hi + ch * 72 + seg * 8);
        *(uint4*)((char*)g_xT + tbase + sw128(ch * 128 + seg * 16)) = v;
    }
}

// ============================================================================
// K0b: Wqk -> GEMM-B tiled/swizzled fp16
// ============================================================================
__global__ __launch_bounds__(256) void k_convert_w(const float* __restrict__ W) {
    int idx = blockIdx.x * 256 + threadIdx.x;
    int j = idx >> 7, q4 = idx & 127;
    float4 v = *(const float4*)(W + (size_t)j * KDIM + q4 * 4);
    unsigned short hh[4] = {f2h(v.x), f2h(v.y), f2h(v.z), f2h(v.w)};
    uint2 hp;
    hp.x = (uint32_t)hh[1] << 16 | hh[0];
    hp.y = (uint32_t)hh[3] << 16 | hh[2];
    size_t base = ((size_t)(j >> 7) * 8 + (q4 >> 4)) * 16384;
    *(uint2*)((char*)g_wB + base + sw128((j & 127) * 128 + (q4 & 15) * 8)) = hp;
}

// ============================================================================
// K1: HMMA fp16 GEMM qk = x @ Wqk^T; cp.async.bulk 3-stage mbarrier pipeline.
// ============================================================================
#define STG_BYTES 32768          /* A 16KB + B 16KB */
#define GEMM_SMEM (3 * STG_BYTES + 1024)

__global__ __launch_bounds__(256, 2) void k_gemm_mma(const float* __restrict__ bqk) {
    extern __shared__ char dsm[];
    __shared__ long long s_mbar[3];
    const uint32_t dynb  = smem_u32(dsm);
    const uint32_t tile0 = (dynb + 1023) & ~1023u;

    const int tid = threadIdx.x;
    const int wid = tid >> 5, lid = tid & 31;
    const int jt  = blockIdx.x;            // 0..7
    const int mt  = blockIdx.y;            // 0..255
    const int j00 = jt * 128;
    const int m00 = mt * 128;
    const int warp_m = (wid >> 2) * 64;
    const int n0     = (wid & 3) * 32;

    uint32_t mb[3] = {smem_u32(&s_mbar[0]), smem_u32(&s_mbar[1]),
                      smem_u32(&s_mbar[2])};
    if (tid == 0)
#pragma unroll
        for (int s = 0; s < 3; s++) MBAR_INIT(mb[s], 1);
    __syncthreads();

    auto issue = [&](int it) {
        int s = it % 3;
        MBAR_EXPECT_TX(mb[s], STG_BYTES);
        bulk_g2s(tile0 + s * STG_BYTES,
                 (char*)g_xA + ((size_t)mt * 8 + it) * 16384, 16384, mb[s]);
        bulk_g2s(tile0 + s * STG_BYTES + 16384,
                 (char*)g_wB + ((size_t)jt * 8 + it) * 16384, 16384, mb[s]);
    };
    if (tid == 0) { issue(0); issue(1); issue(2); }

    float acc[4][4][4] = {};
    const int a_r = (lid & 15);
    const int a_c = (lid >> 4);
    const int b_r = (lid & 7) + ((lid >> 4) << 3);
    const int b_c = (lid >> 3) & 1;

    for (int it = 0; it < 8; ++it) {
        const int s = it % 3;
        MBAR_WAIT(mb[s], (it / 3) & 1);
        const uint32_t ab = tile0 + s * STG_BYTES;
        const uint32_t bb = ab + 16384;
#pragma unroll
        for (int ks = 0; ks < 4; ++ks) {
            uint32_t ah[4][4], bh[4][2];
#pragma unroll
            for (int mf = 0; mf < 4; mf++) {
                uint32_t off = (uint32_t)(warp_m + mf * 16 + a_r) * 128 +
                               ks * 32 + a_c * 16;
                ldmx4(ah[mf], ab + sw128(off));
            }
#pragma unroll
            for (int nf2 = 0; nf2 < 2; nf2++) {
                uint32_t off = (uint32_t)(n0 + nf2 * 16 + b_r) * 128 +
                               ks * 32 + b_c * 16;
                uint32_t t[4];
                ldmx4(t, bb + sw128(off));
                bh[nf2 * 2][0] = t[0]; bh[nf2 * 2][1] = t[1];
                bh[nf2 * 2 + 1][0] = t[2]; bh[nf2 * 2 + 1][1] = t[3];
            }
#pragma unroll
            for (int mf = 0; mf < 4; mf++)
#pragma unroll
                for (int nf = 0; nf < 4; nf++)
                    mma16816(acc[mf][nf], ah[mf], bh[nf]);
        }
        __syncthreads();
        if (it + 3 < 8 && tid == 0) { FENCE_ASYNC(); issue(it + 3); }
    }

    // ---------------- epilogue ----------------
    unsigned short* s_p0 = (unsigned short*)dsm;               // 128x136
    unsigned short* s_p1 = s_p0 + 128 * 136;
    float*          s_red = (float*)(s_p1 + 128 * 136);        // 2x128

    const bool is_k = (j00 >= CC);
    const int  jbase = (is_k ? j00 - CC : j00) + n0 + 2 * (lid & 3);
    float th[4], bx[4], by[4];
    bool  uhc[4];
#pragma unroll
    for (int nf = 0; nf < 4; nf++) {
        int jch = jbase + nf * 8;
        int j2  = jch >> 1;
        int jm  = j2 & 127;
        th[nf]  = exp2f(-(float)jm * (13.287712379549449f / 128.0f));
        uhc[nf] = (j2 < 128);
        float2 bv = *(const float2*)(bqk + j00 + n0 + nf * 8 + 2 * (lid & 3));
        bx[nf] = bv.x;
        by[nf] = bv.y;
    }

    float fsum[4][2] = {};
#pragma unroll
    for (int mf = 0; mf < 4; mf++)
#pragma unroll
        for (int ri = 0; ri < 2; ri++) {
            int   r_loc = warp_m + mf * 16 + (lid >> 2) + ri * 8;
            int   n  = (m00 + r_loc) & (NPOS - 1);
            float hf = (float)(n >> 6);
            float wf = (float)(n & 63);
#pragma unroll
            for (int nf = 0; nf < 4; nf++) {
                float v0 = acc[mf][nf][ri * 2 + 0] + bx[nf];
                float v1 = acc[mf][nf][ri * 2 + 1] + by[nf];
                float f0 = (v0 > 0.f) ? (v0 + 1.f) : __expf(v0);
                float f1 = (v1 > 0.f) ? (v1 + 1.f) : __expf(v1);
                float s, c;
                __sincosf((uhc[nf] ? hf : wf) * th[nf], &s, &c);
                float ro0 = c * f0 - s * f1;
                float ro1 = c * f1 + s * f0;
                int c_loc = n0 + nf * 8 + 2 * (lid & 3);
                if (!is_k) {
                    s_p0[r_loc * 136 + c_loc]     = f2h(ro0);
                    s_p0[r_loc * 136 + c_loc + 1] = f2h(ro1);
                    s_p1[r_loc * 136 + c_loc]     = f2h(f0);
                    s_p1[r_loc * 136 + c_loc + 1] = f2h(f1);
                } else {
                    s_p0[c_loc * 136 + r_loc]       = f2h(ro0);
                    s_p0[(c_loc + 1) * 136 + r_loc] = f2h(ro1);
                    fsum[nf][0] += f0;
                    fsum[nf][1] += f1;
                }
            }
        }

    if (is_k) {
#pragma unroll
        for (int off = 4; off < 32; off <<= 1)
#pragma unroll
            for (int nf = 0; nf < 4; nf++) {
                fsum[nf][0] += __shfl_xor_sync(0xffffffffu, fsum[nf][0], off);
                fsum[nf][1] += __shfl_xor_sync(0xffffffffu, fsum[nf][1], off);
            }
        if (lid < 4) {
#pragma unroll
            for (int nf = 0; nf < 4; nf++) {
                s_red[(wid >> 2) * 128 + n0 + nf * 8 + 2 * lid]     = fsum[nf][0];
                s_red[(wid >> 2) * 128 + n0 + nf * 8 + 2 * lid + 1] = fsum[nf][1];
            }
        }
    }
    __syncthreads();

    if (!is_k) {
        const int r    = tid >> 1;
        const int half = tid & 1;
        size_t drow = (size_t)(m00 + r) * CC + j00 + half * 64;
        const uint4* sp0 = (const uint4*)(s_p0 + r * 136 + half * 64);
        const uint4* sp1 = (const uint4*)(s_p1 + r * 136 + half * 64);
        uint4* d0 = (uint4*)(g_qr + drow);
        uint4* d1 = (uint4*)(g_qf + drow);
#pragma unroll
        for (int i = 0; i < 8; i++) { d0[i] = sp0[i]; d1[i] = sp1[i]; }
    } else {
        const int b      = m00 >> 12;
        const int n0g    = m00 & (NPOS - 1);
        const int cblk0  = (jt - 4) * 2;
#pragma unroll
        for (int w = 0; w < 8; w++) {
            int id  = tid + w * 256;
            int blk = id >> 9;          // 0..3
            int cb  = blk >> 1, nb = blk & 1;
            int within = id & 511;
            int ch = within >> 3, seg = within & 7;
            size_t base = ((size_t)((b * 8 + cblk0 + cb) * 64) +
                           (n0g >> 6) + nb) * 8192;
            uint4 v = *(const uint4*)(s_p0 + (cb * 64 + ch) * 136 + nb * 64 + seg * 8);
            *(uint4*)((char*)g_krT + base + sw128(ch * 128 + seg * 16)) = v;
        }
        if (tid < 128)
            g_kspart[(size_t)mt * CC + (jt - 4) * 128 + tid] =
                s_red[tid] + s_red[128 + tid];
    }
}

// ============================================================================
// K1c: ksum final
// ============================================================================
__global__ void k_ksum_final() {
    int idx = blockIdx.x * 256 + threadIdx.x;  // 0..4095
    if (idx < BB * CC) {
        int b = idx >> 9, ch = idx & 511;
        float s = 0.f;
        for (int mt = b * 32; mt < b * 32 + 32; mt++)
            s += g_kspart[(size_t)mt * CC + ch];
        g_ksum[idx] = s;
    }
}

// ============================================================================
// K2: kv partials via HMMA + bulk-copy pipeline over pre-swizzled 8KB tiles
// ============================================================================
#define KV_STG 16384
#define KV_SMEM (3 * KV_STG + 1024)

__global__ __launch_bounds__(128) void k_kv_mma() {
    extern __shared__ char ksm[];
    __shared__ long long s_mbar[3];
    const uint32_t dynb  = smem_u32(ksm);
    const uint32_t tile0 = (dynb + 1023) & ~1023u;
    const int tid = threadIdx.x;
    const int wid = tid >> 5, lid = tid & 31;
    const int chunk = blockIdx.x;          // 0..7
    const int bh    = blockIdx.y;          // 0..63
    const int b = bh >> 3, h = bh & 7;
    const size_t blk0 = (size_t)(b * 8 + h) * 64 + chunk * 8;

    uint32_t mb[3] = {smem_u32(&s_mbar[0]), smem_u32(&s_mbar[1]),
                      smem_u32(&s_mbar[2])};
    if (tid == 0)
#pragma unroll
        for (int s = 0; s < 3; s++) MBAR_INIT(mb[s], 1);
    __syncthreads();

    auto issue = [&](int it) {
        int s = it % 3;
        MBAR_EXPECT_TX(mb[s], KV_STG);
        bulk_g2s(tile0 + s * KV_STG, (char*)g_krT + (blk0 + it) * 8192, 8192, mb[s]);
        bulk_g2s(tile0 + s * KV_STG + 8192, (char*)g_xT + (blk0 + it) * 8192, 8192,
                 mb[s]);
    };
    if (tid == 0) { issue(0); issue(1); issue(2); }

    float acc[8][4] = {};
    const int a_r = (lid & 15);
    const int a_c = (lid >> 4);
    const int b_r = (lid & 7) + ((lid >> 4) << 3);
    const int b_c = (lid >> 3) & 1;

    for (int it = 0; it < 8; ++it) {
        const int s = it % 3;
        MBAR_WAIT(mb[s], (it / 3) & 1);
        const uint32_t ab = tile0 + s * KV_STG;
        const uint32_t bb = ab + 8192;
#pragma unroll
        for (int ks = 0; ks < 4; ++ks) {
            uint32_t ah[4];
            ldmx4(ah, ab + sw128((uint32_t)(wid * 16 + a_r) * 128 + ks * 32 + a_c * 16));
            uint32_t bhf[8][2];
#pragma unroll
            for (int e2 = 0; e2 < 4; e2++) {
                uint32_t t[4];
                ldmx4(t, bb + sw128((uint32_t)(e2 * 16 + b_r) * 128 + ks * 32 + b_c * 16));
                bhf[e2 * 2][0] = t[0]; bhf[e2 * 2][1] = t[1];
                bhf[e2 * 2 + 1][0] = t[2]; bhf[e2 * 2 + 1][1] = t[3];
            }
#pragma unroll
            for (int ef = 0; ef < 8; ef++) mma16816(acc[ef], ah, bhf[ef]);
        }
        __syncthreads();
        if (it + 3 < 8 && tid == 0) { FENCE_ASYNC(); issue(it + 3); }
    }

    float* dst = g_kv_part + (size_t)(chunk * 64 + bh) * (DH * DH);
    const int r0 = wid * 16 + (lid >> 2);
    const int c0 = 2 * (lid & 3);
#pragma unroll
    for (int ef = 0; ef < 8; ef++) {
        *(float2*)&dst[r0 * DH + ef * 8 + c0] = make_float2(acc[ef][0], acc[ef][1]);
        *(float2*)&dst[(r0 + 8) * DH + ef * 8 + c0] = make_float2(acc[ef][2], acc[ef][3]);
    }
}

// kv final: sum partials, scale 1/n, write TRANSPOSED fp16 kv^T [bh][e][d]
__global__ void k_kv_final() {
    int idx = blockIdx.x * 256 + threadIdx.x;   // bh*4096 + d*64 + e (coalesced reads)
    float s = 0.f;
    for (int c2 = 0; c2 < 8; c2++) s += g_kv_part[(size_t)c2 * 64 * DH * DH + idx];
    int bh = idx >> 12;
    int d  = (idx >> 6) & 63;
    int e  = idx & 63;
    g_kvT[(bh << 12) + e * 64 + d] = f2h(s * (1.0f / (float)NPOS));
}

// ============================================================================
// K3: out = (q_rope @ kv) * z + LePE(x)
// q_rope@kv on HMMA (kv^T fp16 B operand); result staged through smem;
// LePE epilogue vectorized (float4 taps).
// ============================================================================
#define KOUT_DYN (1024 + 8192 + 8192 + 64 * 68 * 4)   /* 34816 */

__global__ __launch_bounds__(256) void k_out(const float* __restrict__ x,
                                             const float* __restrict__ lepe_w,
                                             const float* __restrict__ lepe_b,
                                             float* __restrict__ out) {
    extern __shared__ char kob[];
    __shared__ float s_z[64];
    __shared__ float s_km[64];

    const uint32_t dynb  = smem_u32(kob);
    const uint32_t base  = (dynb + 1023) & ~1023u;
    char*  bp     = kob + (base - dynb);
    const uint32_t qr_u  = base;          // 8KB: q_rope tile, sw128
    const uint32_t kvT_u = base + 8192;   // 8KB: kv^T tile, sw128
    float* s_out = (float*)(bp + 16384);  // 64x68 fp32: qfeat then HMMA result

    int ntile = blockIdx.x;
    int hh    = blockIdx.y;
    int b     = blockIdx.z;
    int tid   = threadIdx.x;
    int n0    = ntile * 64;

    // ---- phase A loads: qfeat (fp32 into s_out), q_rope tile, kvT tile, km
#pragma unroll
    for (int i = 0; i < 4; i++) {
        int f = tid + i * 256;
        int r = f >> 4, cu = f & 15;
        uint2 v = *(const uint2*)(g_qf + (size_t)(b * NPOS + n0 + r) * CC +
                                  hh * DH + cu * 4);
        s_out[r * 68 + cu * 4 + 0] = h2f((unsigned short)(v.x & 0xffff));
        s_out[r * 68 + cu * 4 + 1] = h2f((unsigned short)(v.x >> 16));
        s_out[r * 68 + cu * 4 + 2] = h2f((unsigned short)(v.y & 0xffff));
        s_out[r * 68 + cu * 4 + 3] = h2f((unsigned short)(v.y >> 16));
    }
#pragma unroll
    for (int w = 0; w < 2; w++) {
        int id = tid + w * 256;
        int r = id >> 3, seg = id & 7;
        uint4 v = *(const uint4*)(g_qr + (size_t)(b * NPOS + n0 + r) * CC +
                                  hh * DH + seg * 8);
        *(uint4*)(bp + sw128(r * 128 + seg * 16)) = v;
        uint4 kvv = *(const uint4*)(g_kvT + ((b * NH + hh) << 12) + r * 64 + seg * 8);
        *(uint4*)(bp + 8192 + sw128(r * 128 + seg * 16)) = kvv;
    }
    if (tid < 64) s_km[tid] = g_ksum[b * CC + hh * DH + tid] * (1.0f / (float)NPOS);
    __syncthreads();

    // ---- z = 1/(qfeat . kmean + eps)
    if (tid < 64) {
        float dot = 0.f;
#pragma unroll
        for (int dd = 0; dd < 64; dd++) dot += s_out[tid * 68 + dd] * s_km[dd];
        s_z[tid] = 1.0f / (dot + 1e-6f);
    }
    __syncthreads();

    // ---- HMMA: (64n x 64d) @ (64d x 64e); warp tile m16 x n32
    {
        const int wid = tid >> 5, lid = tid & 31;
        const int mrow = (wid & 3) * 16;
        const int ncol = (wid >> 2) * 32;
        const int a_r = (lid & 15);
        const int a_c = (lid >> 4);
        const int b_r = (lid & 7) + ((lid >> 4) << 3);
        const int b_c = (lid >> 3) & 1;
        float acc[4][4] = {};
#pragma unroll
        for (int ks = 0; ks < 4; ++ks) {
            uint32_t ah[4];
            ldmx4(ah, qr_u + sw128((uint32_t)(mrow + a_r) * 128 + ks * 32 + a_c * 16));
            uint32_t bh[4][2];
#pragma unroll
            for (int nf2 = 0; nf2 < 2; nf2++) {
                uint32_t t[4];
                ldmx4(t, kvT_u + sw128((uint32_t)(ncol + nf2 * 16 + b_r) * 128 +
                                       ks * 32 + b_c * 16));
                bh[nf2 * 2][0] = t[0]; bh[nf2 * 2][1] = t[1];
                bh[nf2 * 2 + 1][0] = t[2]; bh[nf2 * 2 + 1][1] = t[3];
            }
#pragma unroll
            for (int nf = 0; nf < 4; nf++) mma16816(acc[nf], ah, bh[nf]);
        }
        __syncthreads();   // everyone done reading s_out (qfeat) for z
#pragma unroll
        for (int nf = 0; nf < 4; nf++) {
            int rr = mrow + (lid >> 2);
            int cc = ncol + nf * 8 + 2 * (lid & 3);
            s_out[rr * 68 + cc]       = acc[nf][0];
            s_out[rr * 68 + cc + 1]   = acc[nf][1];
            s_out[(rr + 8) * 68 + cc]     = acc[nf][2];
            s_out[(rr + 8) * 68 + cc + 1] = acc[nf][3];
        }
    }
    __syncthreads();

    // ---- LePE + z epilogue
    int ty = tid >> 4, tx = tid & 15;
    int r0 = ty * 4, e0 = tx * 4;
    const int hi = ntile;
    float wloc[4][9], bloc[4];
#pragma unroll
    for (int j = 0; j < 4; j++) {
        int ch = hh * DH + e0 + j;
        bloc[j] = lepe_b[ch];
#pragma unroll
        for (int q = 0; q < 9; q++) wloc[j][q] = lepe_w[ch * 9 + q];
    }
#pragma unroll
    for (int ri = 0; ri < 4; ri++) {
        int r  = r0 + ri;
        int wi = r;
        int nn = n0 + r;
        float z = s_z[r];
        float4 av = *(const float4*)&s_out[r * 68 + e0];
        float pe[4] = {bloc[0], bloc[1], bloc[2], bloc[3]};
#pragma unroll
        for (int dy = -1; dy <= 1; dy++) {
            int y = hi + dy;
            if ((unsigned)y < 64u) {
#pragma unroll
                for (int dx = -1; dx <= 1; dx++) {
                    int xw = wi + dx;
                    if ((unsigned)xw < 64u) {
                        float4 xv = *(const float4*)(
                            x + ((size_t)b * NPOS + y * 64 + xw) * CC +
                            hh * DH + e0);
                        int q = (dy + 1) * 3 + dx + 1;
                        pe[0] += wloc[0][q] * xv.x;
                        pe[1] += wloc[1][q] * xv.y;
                        pe[2] += wloc[2][q] * xv.z;
                        pe[3] += wloc[3][q] * xv.w;
                    }
                }
            }
        }
        float4 ov = make_float4(av.x * z + pe[0], av.y * z + pe[1],
                                av.z * z + pe[2], av.w * z + pe[3]);
        *(float4*)(out + ((size_t)b * NPOS + nn) * CC + hh * DH + e0) = ov;
    }
}

// ============================================================================
extern "C" void kernel_launch(void* const* d_in, const int* in_sizes, int n_in,
                              void* d_out, int out_size) {
    const float *x = nullptr, *Wqk = nullptr, *bqk = nullptr;
    const float *lw = nullptr, *lb = nullptr;
    for (int i = 0; i < n_in; i++) {
        switch (in_sizes[i]) {
            case BB * NPOS * CC: x   = (const float*)d_in[i]; break;
            case 2 * CC * CC:    Wqk = (const float*)d_in[i]; break;
            case 2 * CC:         bqk = (const float*)d_in[i]; break;
            case CC * 9:         lw  = (const float*)d_in[i]; break;
            case CC:             lb  = (const float*)d_in[i]; break;
            default: break;  // h, w scalars
        }
    }
    float* out = (float*)d_out;

    cudaFuncSetAttribute(k_gemm_mma, cudaFuncAttributeMaxDynamicSharedMemorySize,
                         GEMM_SMEM);
    cudaFuncSetAttribute(k_kv_mma, cudaFuncAttributeMaxDynamicSharedMemorySize,
                         KV_SMEM);
    cudaFuncSetAttribute(k_out, cudaFuncAttributeMaxDynamicSharedMemorySize,
                         KOUT_DYN);

    // 4 prep launches + convert_w => k_gemm_mma is launch index 5 (ncu -s 5 -c 1)
    k_prep_x<<<dim3(8, 64, 2), 256>>>(x, 0);
    k_prep_x<<<dim3(8, 64, 2), 256>>>(x, 2);
    k_prep_x<<<dim3(8, 64, 2), 256>>>(x, 4);
    k_prep_x<<<dim3(8, 64, 2), 256>>>(x, 6);
    k_convert_w<<<512, 256>>>(Wqk);
    k_gemm_mma<<<dim3(8, 256), 256, GEMM_SMEM>>>(bqk);
    k_ksum_final<<<16, 256>>>();
    k_kv_mma<<<dim3(8, 64), 128, KV_SMEM>>>();
    k_kv_final<<<1024, 256>>>();
    k_out<<<dim3(64, 8, 8), 256, KOUT_DYN>>>(x, lw, lb, out);
}